// round 4
// baseline (speedup 1.0000x reference)
// R1 resubmit: identical to R0 design — prior bench was an infra failure
// (GB300 container failed twice), no kernel signal. Establish baseline.
#include <cuda_runtime.h>
#include <cstdint>

#define T_TOK 1024
#define H_DIM 1024
#define NE 32
#define TOPK 4
#define F_DIM 1024
#define TWO_F 2048
#define LIMIT 7.0f
#define ALPHA 1.702f
#define EPS 1e-5f

#define BM 128
#define BN 64
#define BK 16
#define APAD 4
#define BPAD 8   // Bs stride 72 -> conflict-free frag loads

// ------------------- scratch (static device allocations) -------------------
__device__ float g_tnorm[T_TOK * H_DIM];            // 4 MB
__device__ int   g_counts[NE];
__device__ int   g_bases[NE];
__device__ int   g_expert_ids[T_TOK * TOPK];
__device__ float g_weights[T_TOK * TOPK];
__device__ int   g_slot_token[T_TOK * TOPK];
__device__ float g_slot_weight[T_TOK * TOPK];
__device__ int   g_token_slot[T_TOK * TOPK];
__device__ float g_act[(size_t)T_TOK * TOPK * F_DIM]; // 16 MB
__device__ float g_y[(size_t)T_TOK * TOPK * H_DIM];   // 16 MB

// ------------------- helpers -------------------
__device__ __forceinline__ uint32_t f2tf(float x) {
    uint32_t r;
    asm("cvt.rna.tf32.f32 %0, %1;" : "=r"(r) : "f"(x));
    return r;
}

__device__ __forceinline__ void mma_tf32(float (&d)[4], const uint32_t (&a)[4],
                                         const uint32_t (&b)[2]) {
    asm volatile(
        "mma.sync.aligned.m16n8k8.row.col.f32.tf32.tf32.f32 "
        "{%0,%1,%2,%3}, {%4,%5,%6,%7}, {%8,%9}, {%0,%1,%2,%3};\n"
        : "+f"(d[0]), "+f"(d[1]), "+f"(d[2]), "+f"(d[3])
        : "r"(a[0]), "r"(a[1]), "r"(a[2]), "r"(a[3]), "r"(b[0]), "r"(b[1]));
}

// ------------------- kernel 0: reset counts -------------------
__global__ void k_zero() {
    if (threadIdx.x < NE) g_counts[threadIdx.x] = 0;
}

// ------------------- kernel 1: rmsnorm + gate + top4 + softmax -------------------
__global__ void k_gate(const float* __restrict__ x, const float* __restrict__ scale,
                       const float* __restrict__ gw, const float* __restrict__ gb) {
    int t = blockIdx.x;
    int tid = threadIdx.x;
    __shared__ float sh[H_DIM];
    __shared__ float red[8];
    __shared__ float logits[NE];
    const float* xr = x + (size_t)t * H_DIM;

    float ss = 0.f;
    for (int i = tid; i < H_DIM; i += 256) { float v = xr[i]; ss += v * v; }
    for (int o = 16; o; o >>= 1) ss += __shfl_xor_sync(~0u, ss, o);
    int warp = tid >> 5, lane = tid & 31;
    if (!lane) red[warp] = ss;
    __syncthreads();
    if (tid < 8) {
        float s = red[tid];
        for (int o = 4; o; o >>= 1) s += __shfl_xor_sync(0xffu, s, o);
        if (!tid) red[0] = s;
    }
    __syncthreads();
    float inv = rsqrtf(red[0] * (1.0f / H_DIM) + EPS);
    for (int i = tid; i < H_DIM; i += 256) {
        float v = xr[i] * inv * scale[i];
        sh[i] = v;
        g_tnorm[(size_t)t * H_DIM + i] = v;
    }
    __syncthreads();
    for (int e = warp; e < NE; e += 8) {
        const float* w = gw + (size_t)e * H_DIM;
        float s = 0.f;
        for (int i = lane; i < H_DIM; i += 32) s += sh[i] * w[i];
        for (int o = 16; o; o >>= 1) s += __shfl_xor_sync(~0u, s, o);
        if (!lane) logits[e] = s + gb[e];
    }
    __syncthreads();
    if (tid == 0) {
        unsigned used = 0;
        float v[TOPK]; int ix[TOPK];
        for (int k = 0; k < TOPK; k++) {
            float best = -3.4e38f; int bi = 0;
            for (int e2 = 0; e2 < NE; e2++)
                if (!((used >> e2) & 1u) && logits[e2] > best) { best = logits[e2]; bi = e2; }
            used |= 1u << bi; v[k] = best; ix[k] = bi;
        }
        float mx = v[0], sum = 0.f, w4[TOPK];
        for (int k = 0; k < TOPK; k++) { w4[k] = __expf(v[k] - mx); sum += w4[k]; }
        float rs = 1.f / sum;
        for (int k = 0; k < TOPK; k++) {
            g_expert_ids[t * TOPK + k] = ix[k];
            g_weights[t * TOPK + k] = w4[k] * rs;
            atomicAdd(&g_counts[ix[k]], 1);
        }
    }
}

// ------------------- kernel 2: deterministic scatter into per-expert lists ----
__global__ void k_scatter() {
    int e = threadIdx.x >> 5;   // 32 warps, one expert each
    int lane = threadIdx.x & 31;
    int base = 0;
    for (int i = 0; i < e; i++) base += g_counts[i];
    if (!lane) g_bases[e] = base;
    int running = 0;
    for (int j0 = 0; j0 < T_TOK * TOPK; j0 += 32) {
        int j = j0 + lane;
        int ee = g_expert_ids[j];
        unsigned m = __ballot_sync(~0u, ee == e);
        if (ee == e) {
            int slot = base + running + __popc(m & ((1u << lane) - 1u));
            g_slot_token[slot] = j >> 2;
            g_slot_weight[slot] = g_weights[j];
            g_token_slot[j] = slot;
        }
        running += __popc(m);
    }
}

// ------------------- kernel 3/4: per-expert tf32 tensor-core GEMM ------------
// IS_G1=1: act[slot,f] = w_slot * swiglu(tnorm[token] @ w1[e]^T + b1[e])
// IS_G1=0: y[slot,h]   = act[slot,:] @ w2[e]^T
template <int IS_G1>
__global__ __launch_bounds__(256, 2) void k_gemm(const float* __restrict__ W,
                                                 const float* __restrict__ bias) {
    const int Kd = 1024;
    const int Nd = IS_G1 ? TWO_F : H_DIM;
    const int e = blockIdx.z;
    const int cnt = g_counts[e];
    const int m0 = blockIdx.y * BM;
    if (m0 >= cnt) return;
    const int base = g_bases[e];
    const int n0 = blockIdx.x * BN;

    __shared__ float As[BM][BK + APAD];
    __shared__ float Bs[BK][BN + BPAD];

    const int tid = threadIdx.x;
    const int warp = tid >> 5, lane = tid & 31;
    const int g = lane >> 2, tg = lane & 3;
    const int wm = (warp & 3) * 32;
    const int wn = (warp >> 2) * 32;

    // A-load mapping: 512 float4 per tile, 2 per thread
    const int ar0 = tid >> 2;      // 0..63
    const int ar1 = ar0 + 64;      // 64..127
    const int ac4 = (tid & 3) * 4; // k offset
    const float* aptr0 = nullptr;
    const float* aptr1 = nullptr;
    if (m0 + ar0 < cnt) {
        int r = base + m0 + ar0;
        aptr0 = IS_G1 ? (g_tnorm + (size_t)g_slot_token[r] * H_DIM)
                      : (g_act + (size_t)r * F_DIM);
    }
    if (m0 + ar1 < cnt) {
        int r = base + m0 + ar1;
        aptr1 = IS_G1 ? (g_tnorm + (size_t)g_slot_token[r] * H_DIM)
                      : (g_act + (size_t)r * F_DIM);
    }
    // B-load mapping: 256 float4 per tile, 1 per thread
    const int br = tid >> 2; // output-col row of W, 0..63
    const float* Wb = W + (size_t)e * Nd * Kd;
    const float* bptr = Wb + (size_t)(n0 + br) * Kd + ac4;

    float acc[2][4][4];
#pragma unroll
    for (int mi = 0; mi < 2; mi++)
#pragma unroll
        for (int ni = 0; ni < 4; ni++)
#pragma unroll
            for (int q = 0; q < 4; q++) acc[mi][ni][q] = 0.f;

    for (int k0 = 0; k0 < Kd; k0 += BK) {
        float4 av0 = aptr0 ? *(const float4*)(aptr0 + k0 + ac4) : make_float4(0, 0, 0, 0);
        float4 av1 = aptr1 ? *(const float4*)(aptr1 + k0 + ac4) : make_float4(0, 0, 0, 0);
        float4 bv = *(const float4*)(bptr + k0);
        *(float4*)&As[ar0][ac4] = av0;
        *(float4*)&As[ar1][ac4] = av1;
        Bs[ac4 + 0][br] = bv.x;
        Bs[ac4 + 1][br] = bv.y;
        Bs[ac4 + 2][br] = bv.z;
        Bs[ac4 + 3][br] = bv.w;
        __syncthreads();
#pragma unroll
        for (int kk = 0; kk < BK; kk += 8) {
            uint32_t a[2][4], b[4][2];
#pragma unroll
            for (int mi = 0; mi < 2; mi++) {
                int rb = wm + mi * 16;
                a[mi][0] = f2tf(As[rb + g][kk + tg]);
                a[mi][1] = f2tf(As[rb + g + 8][kk + tg]);
                a[mi][2] = f2tf(As[rb + g][kk + tg + 4]);
                a[mi][3] = f2tf(As[rb + g + 8][kk + tg + 4]);
            }
#pragma unroll
            for (int ni = 0; ni < 4; ni++) {
                int cb = wn + ni * 8 + g;
                b[ni][0] = f2tf(Bs[kk + tg][cb]);
                b[ni][1] = f2tf(Bs[kk + tg + 4][cb]);
            }
#pragma unroll
            for (int mi = 0; mi < 2; mi++)
#pragma unroll
                for (int ni = 0; ni < 4; ni++) mma_tf32(acc[mi][ni], a[mi], b[ni]);
        }
        __syncthreads();
    }

    // epilogue
#pragma unroll
    for (int mi = 0; mi < 2; mi++) {
#pragma unroll
        for (int ni = 0; ni < 4; ni++) {
            int ceven = n0 + wn + ni * 8 + 2 * tg;
#pragma unroll
            for (int h2 = 0; h2 < 2; h2++) {
                int r = m0 + wm + mi * 16 + g + h2 * 8;
                if (r >= cnt) continue;
                int slot = base + r;
                float v0 = acc[mi][ni][h2 * 2 + 0];
                float v1 = acc[mi][ni][h2 * 2 + 1];
                if (IS_G1) {
                    float glu = fminf(v0 + bias[e * TWO_F + ceven], LIMIT);
                    float lin = fminf(fmaxf(v1 + bias[e * TWO_F + ceven + 1], -LIMIT), LIMIT);
                    float act = glu * (1.f / (1.f + __expf(-ALPHA * glu))) * (lin + 1.f);
                    g_act[(size_t)slot * F_DIM + (ceven >> 1)] = g_slot_weight[slot] * act;
                } else {
                    g_y[(size_t)slot * H_DIM + ceven] = v0;
                    g_y[(size_t)slot * H_DIM + ceven + 1] = v1;
                }
            }
        }
    }
}

// ------------------- kernel 5: combine + residual + b2 -------------------
__global__ void k_combine(const float* __restrict__ x, const float* __restrict__ b2,
                          float* __restrict__ out) {
    int t = blockIdx.x, tid = threadIdx.x;
    int s0 = g_token_slot[t * 4 + 0], s1 = g_token_slot[t * 4 + 1];
    int s2 = g_token_slot[t * 4 + 2], s3 = g_token_slot[t * 4 + 3];
    int e0 = g_expert_ids[t * 4 + 0], e1 = g_expert_ids[t * 4 + 1];
    int e2 = g_expert_ids[t * 4 + 2], e3 = g_expert_ids[t * 4 + 3];
    float w0 = g_weights[t * 4 + 0], w1v = g_weights[t * 4 + 1];
    float w2v = g_weights[t * 4 + 2], w3 = g_weights[t * 4 + 3];
    for (int i = tid; i < H_DIM; i += 256) {
        float v = x[(size_t)t * H_DIM + i];
        v += g_y[(size_t)s0 * H_DIM + i] + w0 * b2[(size_t)e0 * H_DIM + i];
        v += g_y[(size_t)s1 * H_DIM + i] + w1v * b2[(size_t)e1 * H_DIM + i];
        v += g_y[(size_t)s2 * H_DIM + i] + w2v * b2[(size_t)e2 * H_DIM + i];
        v += g_y[(size_t)s3 * H_DIM + i] + w3 * b2[(size_t)e3 * H_DIM + i];
        out[(size_t)t * H_DIM + i] = v;
    }
}

// ------------------- launcher -------------------
extern "C" void kernel_launch(void* const* d_in, const int* in_sizes, int n_in,
                              void* d_out, int out_size) {
    const float* x = (const float*)d_in[0];
    const float* norm_scale = (const float*)d_in[1];
    const float* gate_w = (const float*)d_in[2];
    const float* gate_b = (const float*)d_in[3];
    const float* w1 = (const float*)d_in[4];
    const float* b1 = (const float*)d_in[5];
    const float* w2 = (const float*)d_in[6];
    const float* b2 = (const float*)d_in[7];
    float* out = (float*)d_out;

    k_zero<<<1, 32>>>();
    k_gate<<<T_TOK, 256>>>(x, norm_scale, gate_w, gate_b);
    k_scatter<<<1, 1024>>>();
    dim3 grid1(TWO_F / BN, T_TOK / BM, NE); // (32, 8, 32)
    k_gemm<1><<<grid1, 256>>>(w1, b1);
    dim3 grid2(H_DIM / BN, T_TOK / BM, NE); // (16, 8, 32)
    k_gemm<0><<<grid2, 256>>>(w2, nullptr);
    k_combine<<<T_TOK, 256>>>(x, b2, out);
}

// round 7
// speedup vs baseline: 1.4072x; 1.4072x over previous
// R5: attack measured L1-bound GEMM (75.7% L1, 28% tensor):
//  - warp tile 32x32 -> 64x32 (LDS/MMA 4.0 -> 1.5), BN 64 -> 128
//  - drop cvt.rna.tf32 (feed fp32 bits, HW truncates; alu pipe relief)
//  - cp.async 2-stage double buffering (overlap gmem->smem with MMA)
#include <cuda_runtime.h>
#include <cstdint>

#define T_TOK 1024
#define H_DIM 1024
#define NE 32
#define TOPK 4
#define F_DIM 1024
#define TWO_F 2048
#define LIMIT 7.0f
#define ALPHA 1.702f
#define EPS 1e-5f

#define BM 128
#define BN 128
#define BK 16
#define LDA (BK + 4)   // 20-float stride: 16B-aligned rows, conflict-free frags

// ------------------- scratch -------------------
__device__ float g_tnorm[T_TOK * H_DIM];
__device__ int   g_counts[NE];
__device__ int   g_bases[NE];
__device__ int   g_expert_ids[T_TOK * TOPK];
__device__ float g_weights[T_TOK * TOPK];
__device__ int   g_slot_token[T_TOK * TOPK];
__device__ float g_slot_weight[T_TOK * TOPK];
__device__ int   g_token_slot[T_TOK * TOPK];
__device__ float g_act[(size_t)T_TOK * TOPK * F_DIM];
__device__ float g_y[(size_t)T_TOK * TOPK * H_DIM];

// ------------------- helpers -------------------
__device__ __forceinline__ void mma_tf32(float (&d)[4], const uint32_t (&a)[4],
                                         const uint32_t (&b)[2]) {
    asm volatile(
        "mma.sync.aligned.m16n8k8.row.col.f32.tf32.tf32.f32 "
        "{%0,%1,%2,%3}, {%4,%5,%6,%7}, {%8,%9}, {%0,%1,%2,%3};\n"
        : "+f"(d[0]), "+f"(d[1]), "+f"(d[2]), "+f"(d[3])
        : "r"(a[0]), "r"(a[1]), "r"(a[2]), "r"(a[3]), "r"(b[0]), "r"(b[1]));
}

__device__ __forceinline__ void cp16(uint32_t dst, const float* src, uint32_t sz) {
    asm volatile("cp.async.ca.shared.global [%0], [%1], 16, %2;\n"
                 ::"r"(dst), "l"(src), "r"(sz));
}
__device__ __forceinline__ void cp_commit() { asm volatile("cp.async.commit_group;\n"); }
template <int N>
__device__ __forceinline__ void cp_wait() {
    asm volatile("cp.async.wait_group %0;\n" ::"n"(N));
}

// ------------------- kernel 0: reset counts -------------------
__global__ void k_zero() {
    if (threadIdx.x < NE) g_counts[threadIdx.x] = 0;
}

// ------------------- kernel 1: rmsnorm + gate + top4 + softmax ----------------
__global__ void k_gate(const float* __restrict__ x, const float* __restrict__ scale,
                       const float* __restrict__ gw, const float* __restrict__ gb) {
    int t = blockIdx.x;
    int tid = threadIdx.x;
    __shared__ float sh[H_DIM];
    __shared__ float red[8];
    __shared__ float logits[NE];
    const float* xr = x + (size_t)t * H_DIM;

    float ss = 0.f;
    for (int i = tid; i < H_DIM; i += 256) { float v = xr[i]; ss += v * v; }
    for (int o = 16; o; o >>= 1) ss += __shfl_xor_sync(~0u, ss, o);
    int warp = tid >> 5, lane = tid & 31;
    if (!lane) red[warp] = ss;
    __syncthreads();
    if (tid < 8) {
        float s = red[tid];
        for (int o = 4; o; o >>= 1) s += __shfl_xor_sync(0xffu, s, o);
        if (!tid) red[0] = s;
    }
    __syncthreads();
    float inv = rsqrtf(red[0] * (1.0f / H_DIM) + EPS);
    for (int i = tid; i < H_DIM; i += 256) {
        float v = xr[i] * inv * scale[i];
        sh[i] = v;
        g_tnorm[(size_t)t * H_DIM + i] = v;
    }
    __syncthreads();
    for (int e = warp; e < NE; e += 8) {
        const float* w = gw + (size_t)e * H_DIM;
        float s = 0.f;
        for (int i = lane; i < H_DIM; i += 32) s += sh[i] * w[i];
        for (int o = 16; o; o >>= 1) s += __shfl_xor_sync(~0u, s, o);
        if (!lane) logits[e] = s + gb[e];
    }
    __syncthreads();
    if (tid == 0) {
        unsigned used = 0;
        float v[TOPK]; int ix[TOPK];
        for (int k = 0; k < TOPK; k++) {
            float best = -3.4e38f; int bi = 0;
            for (int e2 = 0; e2 < NE; e2++)
                if (!((used >> e2) & 1u) && logits[e2] > best) { best = logits[e2]; bi = e2; }
            used |= 1u << bi; v[k] = best; ix[k] = bi;
        }
        float mx = v[0], sum = 0.f, w4[TOPK];
        for (int k = 0; k < TOPK; k++) { w4[k] = __expf(v[k] - mx); sum += w4[k]; }
        float rs = 1.f / sum;
        for (int k = 0; k < TOPK; k++) {
            g_expert_ids[t * TOPK + k] = ix[k];
            g_weights[t * TOPK + k] = w4[k] * rs;
            atomicAdd(&g_counts[ix[k]], 1);
        }
    }
}

// ------------------- kernel 2: deterministic scatter --------------------------
__global__ void k_scatter() {
    int e = threadIdx.x >> 5;
    int lane = threadIdx.x & 31;
    int base = 0;
    for (int i = 0; i < e; i++) base += g_counts[i];
    if (!lane) g_bases[e] = base;
    int running = 0;
    for (int j0 = 0; j0 < T_TOK * TOPK; j0 += 32) {
        int j = j0 + lane;
        int ee = g_expert_ids[j];
        unsigned m = __ballot_sync(~0u, ee == e);
        if (ee == e) {
            int slot = base + running + __popc(m & ((1u << lane) - 1u));
            g_slot_token[slot] = j >> 2;
            g_slot_weight[slot] = g_weights[j];
            g_token_slot[j] = slot;
        }
        running += __popc(m);
    }
}

// ------------------- kernel 3/4: tf32 tensor GEMM, cp.async 2-stage -----------
// IS_G1=1: act[slot,f] = w_slot * swiglu(tnorm[token] @ w1[e]^T + b1[e])
// IS_G1=0: y[slot,h]   = act[slot,:] @ w2[e]^T
template <int IS_G1>
__global__ __launch_bounds__(256, 2) void k_gemm(const float* __restrict__ W,
                                                 const float* __restrict__ bias) {
    const int Kd = 1024;
    const int Nd = IS_G1 ? TWO_F : H_DIM;
    const int e = blockIdx.z;
    const int cnt = g_counts[e];
    const int m0 = blockIdx.y * BM;
    if (m0 >= cnt) return;
    const int base = g_bases[e];
    const int n0 = blockIdx.x * BN;

    __shared__ float As[2][BM][LDA];
    __shared__ float Bs[2][BN][LDA];

    const int tid = threadIdx.x;
    const int warp = tid >> 5, lane = tid & 31;
    const int g = lane >> 2, tg = lane & 3;
    const int wm = (warp & 1) * 64;    // 2 warp-rows of 64
    const int wn = (warp >> 1) * 32;   // 4 warp-cols of 32

    // ---- loader mapping: 256 threads, each copies 2 A-rows-quads + 2 B ----
    const int lr = tid >> 2;            // 0..63
    const int lk = (tid & 3) * 4;       // k-quad offset 0/4/8/12
    const float* Wb = W + (size_t)e * Nd * Kd;

    const float* a0 = Wb; uint32_t sz0 = 0;
    const float* a1 = Wb; uint32_t sz1 = 0;
    if (m0 + lr < cnt) {
        int s = base + m0 + lr;
        a0 = (IS_G1 ? (g_tnorm + (size_t)g_slot_token[s] * H_DIM)
                    : (g_act + (size_t)s * F_DIM)) + lk;
        sz0 = 16;
    }
    if (m0 + lr + 64 < cnt) {
        int s = base + m0 + lr + 64;
        a1 = (IS_G1 ? (g_tnorm + (size_t)g_slot_token[s] * H_DIM)
                    : (g_act + (size_t)s * F_DIM)) + lk;
        sz1 = 16;
    }
    const float* b0 = Wb + (size_t)(n0 + lr) * Kd + lk;
    const float* b1 = Wb + (size_t)(n0 + lr + 64) * Kd + lk;

    uint32_t sA0 = (uint32_t)__cvta_generic_to_shared(&As[0][lr][lk]);
    uint32_t sA1 = (uint32_t)__cvta_generic_to_shared(&As[0][lr + 64][lk]);
    uint32_t sB0 = (uint32_t)__cvta_generic_to_shared(&Bs[0][lr][lk]);
    uint32_t sB1 = (uint32_t)__cvta_generic_to_shared(&Bs[0][lr + 64][lk]);
    const uint32_t stA = (uint32_t)sizeof(As[0]);
    const uint32_t stB = (uint32_t)sizeof(Bs[0]);

    float acc[4][4][4];
#pragma unroll
    for (int mi = 0; mi < 4; mi++)
#pragma unroll
        for (int ni = 0; ni < 4; ni++)
#pragma unroll
            for (int q = 0; q < 4; q++) acc[mi][ni][q] = 0.f;

    // prologue: stage 0
    cp16(sA0, a0, sz0);
    cp16(sA1, a1, sz1);
    cp16(sB0, b0, 16);
    cp16(sB1, b1, 16);
    cp_commit();

    const int NIT = Kd / BK;  // 64
#pragma unroll 1
    for (int it = 0; it < NIT; it++) {
        if (it + 1 < NIT) {
            int k0 = (it + 1) * BK;
            uint32_t so = (uint32_t)((it + 1) & 1);
            cp16(sA0 + so * stA, a0 + k0, sz0);
            cp16(sA1 + so * stA, a1 + k0, sz1);
            cp16(sB0 + so * stB, b0 + k0, 16);
            cp16(sB1 + so * stB, b1 + k0, 16);
            cp_commit();
            cp_wait<1>();
        } else {
            cp_wait<0>();
        }
        __syncthreads();
        const int s = it & 1;
#pragma unroll
        for (int kk = 0; kk < BK; kk += 8) {
            uint32_t a[4][4], b[4][2];
#pragma unroll
            for (int mi = 0; mi < 4; mi++) {
                int rb = wm + mi * 16;
                a[mi][0] = __float_as_uint(As[s][rb + g][kk + tg]);
                a[mi][1] = __float_as_uint(As[s][rb + g + 8][kk + tg]);
                a[mi][2] = __float_as_uint(As[s][rb + g][kk + tg + 4]);
                a[mi][3] = __float_as_uint(As[s][rb + g + 8][kk + tg + 4]);
            }
#pragma unroll
            for (int ni = 0; ni < 4; ni++) {
                int cb = wn + ni * 8 + g;
                b[ni][0] = __float_as_uint(Bs[s][cb][kk + tg]);
                b[ni][1] = __float_as_uint(Bs[s][cb][kk + tg + 4]);
            }
#pragma unroll
            for (int mi = 0; mi < 4; mi++)
#pragma unroll
                for (int ni = 0; ni < 4; ni++) mma_tf32(acc[mi][ni], a[mi], b[ni]);
        }
        __syncthreads();
    }

    // ---- epilogue ----
#pragma unroll
    for (int mi = 0; mi < 4; mi++) {
#pragma unroll
        for (int h2 = 0; h2 < 2; h2++) {
            int r = m0 + wm + mi * 16 + g + h2 * 8;
            if (r >= cnt) continue;
            int slot = base + r;
            float wsl = IS_G1 ? g_slot_weight[slot] : 0.f;
#pragma unroll
            for (int ni = 0; ni < 4; ni++) {
                int ceven = n0 + wn + ni * 8 + 2 * tg;
                float v0 = acc[mi][ni][h2 * 2 + 0];
                float v1 = acc[mi][ni][h2 * 2 + 1];
                if (IS_G1) {
                    const float2 bb = *(const float2*)(bias + (size_t)e * TWO_F + ceven);
                    float glu = fminf(v0 + bb.x, LIMIT);
                    float lin = fminf(fmaxf(v1 + bb.y, -LIMIT), LIMIT);
                    float act = glu * (1.f / (1.f + __expf(-ALPHA * glu))) * (lin + 1.f);
                    g_act[(size_t)slot * F_DIM + (ceven >> 1)] = wsl * act;
                } else {
                    *(float2*)(g_y + (size_t)slot * H_DIM + ceven) = make_float2(v0, v1);
                }
            }
        }
    }
}

// ------------------- kernel 5: combine + residual + b2 -------------------
__global__ void k_combine(const float* __restrict__ x, const float* __restrict__ b2,
                          float* __restrict__ out) {
    int t = blockIdx.x, tid = threadIdx.x;
    int s0 = g_token_slot[t * 4 + 0], s1 = g_token_slot[t * 4 + 1];
    int s2 = g_token_slot[t * 4 + 2], s3 = g_token_slot[t * 4 + 3];
    int e0 = g_expert_ids[t * 4 + 0], e1 = g_expert_ids[t * 4 + 1];
    int e2 = g_expert_ids[t * 4 + 2], e3 = g_expert_ids[t * 4 + 3];
    float w0 = g_weights[t * 4 + 0], w1v = g_weights[t * 4 + 1];
    float w2v = g_weights[t * 4 + 2], w3 = g_weights[t * 4 + 3];
    for (int i = tid; i < H_DIM; i += 256) {
        float v = x[(size_t)t * H_DIM + i];
        v += g_y[(size_t)s0 * H_DIM + i] + w0 * b2[(size_t)e0 * H_DIM + i];
        v += g_y[(size_t)s1 * H_DIM + i] + w1v * b2[(size_t)e1 * H_DIM + i];
        v += g_y[(size_t)s2 * H_DIM + i] + w2v * b2[(size_t)e2 * H_DIM + i];
        v += g_y[(size_t)s3 * H_DIM + i] + w3 * b2[(size_t)e3 * H_DIM + i];
        out[(size_t)t * H_DIM + i] = v;
    }
}

// ------------------- launcher -------------------
extern "C" void kernel_launch(void* const* d_in, const int* in_sizes, int n_in,
                              void* d_out, int out_size) {
    const float* x = (const float*)d_in[0];
    const float* norm_scale = (const float*)d_in[1];
    const float* gate_w = (const float*)d_in[2];
    const float* gate_b = (const float*)d_in[3];
    const float* w1 = (const float*)d_in[4];
    const float* b1 = (const float*)d_in[5];
    const float* w2 = (const float*)d_in[6];
    const float* b2 = (const float*)d_in[7];
    float* out = (float*)d_out;

    k_zero<<<1, 32>>>();
    k_gate<<<T_TOK, 256>>>(x, norm_scale, gate_w, gate_b);
    k_scatter<<<1, 1024>>>();
    dim3 grid1(TWO_F / BN, T_TOK / BM, NE); // (16, 8, 32)
    k_gemm<1><<<grid1, 256>>>(w1, b1);
    dim3 grid2(H_DIM / BN, T_TOK / BM, NE); // (8, 8, 32)
    k_gemm<0><<<grid2, 256>>>(w2, nullptr);
    k_combine<<<T_TOK, 256>>>(x, b2, out);
}